// round 1
// baseline (speedup 1.0000x reference)
#include <cuda_runtime.h>

// Problem constants
#define BS   128
#define NR   3
#define CD   64          // data channels
#define CG   3           // gt channels
#define CH   256         // hidden
#define KIN  67          // CD + CG
#define KPAD 68          // padded (even) input dim
#define HW   1024        // 32*32 pixels per image
#define NPAIR (BS * HW / 2)   // 65536 pixel-pairs
#define THREADS 256
#define NBLOCKS (NPAIR / THREADS)  // 256

typedef unsigned long long u64;

// ---- packed f32x2 helpers (sm_103a) ----
__device__ __forceinline__ void fma2(u64 &d, u64 a, u64 b) {
    asm("fma.rn.f32x2 %0, %1, %2, %0;" : "+l"(d) : "l"(a), "l"(b));
}
__device__ __forceinline__ u64 add2(u64 a, u64 b) {
    u64 d; asm("add.rn.f32x2 %0, %1, %2;" : "=l"(d) : "l"(a), "l"(b)); return d;
}
__device__ __forceinline__ u64 pack2(float lo, float hi) {
    u64 d; asm("mov.b64 %0, {%1, %2};" : "=l"(d) : "f"(lo), "f"(hi)); return d;
}
__device__ __forceinline__ void unpack2(u64 v, float &lo, float &hi) {
    asm("mov.b64 {%0, %1}, %2;" : "=f"(lo), "=f"(hi) : "l"(v));
}

// dynamic smem layout: b1s[256] | w3s[256] | W1d[256*68] (u64, duplicated pairs)
#define SMEM_BYTES (CH * 4 * 2 + CH * KPAD * 8)   // 2048 + 139264 = 141312

extern __shared__ unsigned char smem_raw[];

__global__ __launch_bounds__(THREADS, 1)
void qnn_kernel(const float* __restrict__ data, const float* __restrict__ gt,
                const float* __restrict__ W1, const float* __restrict__ b1,
                const float* __restrict__ W3, const float* __restrict__ b3,
                float* __restrict__ out)
{
    float* b1s = (float*)smem_raw;          // 256 floats
    float* w3s = b1s + CH;                  // 256 floats
    u64*   W1d = (u64*)(w3s + CH);          // 256*68 u64, 16B-aligned (offset 2048)

    const int tid = threadIdx.x;
    for (int i = tid; i < CH; i += THREADS) { b1s[i] = b1[i]; w3s[i] = W3[i]; }
    for (int i = tid; i < CH * KPAD; i += THREADS) {
        int o = i / KPAD;
        int k = i - o * KPAD;
        float v = (k < KIN) ? W1[o * KIN + k] : 0.f;
        W1d[i] = pack2(v, v);
    }
    __syncthreads();

    const int g = blockIdx.x * THREADS + tid;   // pixel-pair index
    const int b = g >> 9;                        // 512 pairs per image
    const int p = (g & 511) << 1;                // even pixel within image

    const float bias3 = b3[0];

    // packed input vector for a pixel pair: x2[k] = {x_p(k), x_{p+1}(k)}
    u64 x2[KPAD];
    {
        const u64* gp = (const u64*)(gt + (size_t)b * CG * HW + p);
        x2[64] = gp[0];
        x2[65] = gp[HW / 2];
        x2[66] = gp[HW];
    }
    x2[67] = 0ull;

    float s_lo0, s_lo1, s_lo2, s_hi0, s_hi1, s_hi2;

    #pragma unroll
    for (int n = 0; n < NR; n++) {
        // load 64 data channels for this ref (coalesced 8B per lane per channel)
        const u64* dp = (const u64*)(data + ((size_t)(b * NR + n) * CD) * HW + p);
        #pragma unroll
        for (int c = 0; c < CD; c++) x2[c] = dp[(size_t)c * (HW / 2)];

        float acc_lo = bias3, acc_hi = bias3;

        for (int o = 0; o < CH; o += 2) {
            const ulonglong2* r0 = (const ulonglong2*)(W1d + o * KPAD);
            const ulonglong2* r1 = (const ulonglong2*)(W1d + (o + 1) * KPAD);
            u64 t00 = 0, t01 = 0, t10 = 0, t11 = 0;
            #pragma unroll
            for (int kk = 0; kk < KPAD / 2; kk++) {
                ulonglong2 a0 = r0[kk];   // {W1[o][2kk] dup, W1[o][2kk+1] dup}
                ulonglong2 a1 = r1[kk];
                fma2(t00, a0.x, x2[2 * kk]);
                fma2(t01, a0.y, x2[2 * kk + 1]);
                fma2(t10, a1.x, x2[2 * kk]);
                fma2(t11, a1.y, x2[2 * kk + 1]);
            }
            u64 u0 = add2(t00, t01);
            u64 u1 = add2(t10, t11);
            float l0, h0, l1, h1;
            unpack2(u0, l0, h0);
            unpack2(u1, l1, h1);
            const float bb0 = b1s[o],     bb1 = b1s[o + 1];
            const float w30 = w3s[o],     w31 = w3s[o + 1];
            acc_lo = fmaf(fmaxf(l0 + bb0, 0.f), w30, acc_lo);
            acc_hi = fmaf(fmaxf(h0 + bb0, 0.f), w30, acc_hi);
            acc_lo = fmaf(fmaxf(l1 + bb1, 0.f), w31, acc_lo);
            acc_hi = fmaf(fmaxf(h1 + bb1, 0.f), w31, acc_hi);
        }

        float sl = 1.f / (1.f + __expf(-acc_lo));
        float sh = 1.f / (1.f + __expf(-acc_hi));
        if (n == 0) { s_lo0 = sl; s_hi0 = sh; }
        else if (n == 1) { s_lo1 = sl; s_hi1 = sh; }
        else { s_lo2 = sl; s_hi2 = sh; }
    }

    // normalize over refs
    const float inv_lo = 1.f / (s_lo0 + s_lo1 + s_lo2);
    const float inv_hi = 1.f / (s_hi0 + s_hi1 + s_hi2);
    u64 w2_0 = pack2(s_lo0 * inv_lo, s_hi0 * inv_hi);
    u64 w2_1 = pack2(s_lo1 * inv_lo, s_hi1 * inv_hi);
    u64 w2_2 = pack2(s_lo2 * inv_lo, s_hi2 * inv_hi);

    // write w output: out layout = [z (BS*CD*HW) | w (BS*NR*HW)]
    float* out_w = out + (size_t)BS * CD * HW;
    *((u64*)(out_w + (size_t)(b * NR + 0) * HW + p)) = w2_0;
    *((u64*)(out_w + (size_t)(b * NR + 1) * HW + p)) = w2_1;
    *((u64*)(out_w + (size_t)(b * NR + 2) * HW + p)) = w2_2;

    // z = sum_n data[b,n,c,p] * w[b,n,p]   (re-read data, packed FMA)
    const u64* dbase = (const u64*)(data + (size_t)b * NR * CD * HW + p);
    u64* zbase = (u64*)(out + (size_t)b * CD * HW + p);
    #pragma unroll 8
    for (int c = 0; c < CD; c++) {
        u64 acc = 0;
        u64 d0 = dbase[((size_t)0 * CD + c) * (HW / 2)];
        u64 d1 = dbase[((size_t)1 * CD + c) * (HW / 2)];
        u64 d2 = dbase[((size_t)2 * CD + c) * (HW / 2)];
        fma2(acc, d0, w2_0);
        fma2(acc, d1, w2_1);
        fma2(acc, d2, w2_2);
        zbase[(size_t)c * (HW / 2)] = acc;
    }
}

extern "C" void kernel_launch(void* const* d_in, const int* in_sizes, int n_in,
                              void* d_out, int out_size) {
    const float* data = (const float*)d_in[0];
    const float* gt   = (const float*)d_in[1];
    const float* W1   = (const float*)d_in[2];
    const float* b1   = (const float*)d_in[3];
    const float* W3   = (const float*)d_in[4];
    const float* b3   = (const float*)d_in[5];
    float* out = (float*)d_out;

    cudaFuncSetAttribute(qnn_kernel, cudaFuncAttributeMaxDynamicSharedMemorySize,
                         SMEM_BYTES);
    qnn_kernel<<<NBLOCKS, THREADS, SMEM_BYTES>>>(data, gt, W1, b1, W3, b3, out);
}